// round 15
// baseline (speedup 1.0000x reference)
#include <cuda_runtime.h>
#include <cstdint>
#include <math.h>

constexpr int BB = 64, LQ = 20, LD = 512, DIM = 300, NB = 11, WIN = 5;
constexpr int EQ = 5, ED = 10, DESC = 20, KC = 10;
constexpr int CH = 128, NPAIR = 16, QR_TOT = 64, PSLOTS = 13, NCD = 16, NENT = 15;
constexpr int XSTR = 20;    // entity conv row stride (16 data words)
constexpr int WXS = 36;     // word conv row stride (32 data words)

__constant__ float c_mu[NB]  = {1.0f, 0.9f, 0.7f, 0.5f, 0.3f, 0.1f, -0.1f, -0.3f, -0.5f, -0.7f, -0.9f};
__constant__ float c_nis[NB] = {-500000.0f, -50.0f, -50.0f, -50.0f, -50.0f, -50.0f, -50.0f, -50.0f, -50.0f, -50.0f, -50.0f};
__constant__ int c_pq[NPAIR] = {0,0,0,1,2,1,1,2,2,3,3,3,0,1,2,3};
__constant__ int c_pd[NPAIR] = {0,2,1,0,0,1,2,1,2,0,1,2,3,3,3,3};
__constant__ int c_qoff[4] = {0,20,39,57};
__constant__ int c_qlen[4] = {20,19,18,5};
__constant__ int c_dslot[4] = {0,4,8,12};
__constant__ int c_dnch[4] = {4,4,4,1};

constexpr size_t OFF_QW    = 0;
constexpr size_t OFF_DW    = OFF_QW    + (size_t)BB*LQ*DIM;
constexpr size_t OFF_QBOW  = OFF_DW    + (size_t)BB*LD*DIM;
constexpr size_t OFF_DBOW  = OFF_QBOW  + (size_t)BB*CH;
constexpr size_t OFF_QU    = OFF_DBOW  + (size_t)BB*CH;
constexpr size_t OFF_QB    = OFF_QU    + (size_t)BB*20*CH;
constexpr size_t OFF_QT    = OFF_QB    + (size_t)BB*19*CH;
constexpr size_t OFF_DU    = OFF_QT    + (size_t)BB*18*CH;
constexpr size_t OFF_DB    = OFF_DU    + (size_t)BB*512*CH;
constexpr size_t OFF_DT    = OFF_DB    + (size_t)BB*511*CH;
constexpr size_t OFF_QS    = OFF_DT    + (size_t)BB*510*CH;
constexpr size_t OFF_DS    = OFF_QS    + (size_t)BB*EQ*CH;
constexpr size_t OFF_CS1   = OFF_DS    + (size_t)BB*ED*CH;
constexpr size_t OFF_CS8   = OFF_CS1   + (size_t)BB*DIM;
constexpr size_t OFF_ECONV = OFF_CS8   + (size_t)BB*NCD*DIM;
constexpr size_t OFF_PART  = OFF_ECONV + (size_t)BB*NENT*CH;
constexpr size_t SCRATCH_TOTAL = OFF_PART + (size_t)PSLOTS*BB*QR_TOT*NB;
__device__ float g_scratch[SCRATCH_TOTAL];

// word conv smem: X rows (258*WXS words) + W fragments (K*4096 words, K<=3)
constexpr int WORD_SMEM = (258*WXS + 3*4096) * 4;   // ~86 KB
constexpr int ENT_SMEM  = (160*XSTR + 5*128*XSTR) * 4;

__device__ __forceinline__ uint32_t packbf(float lo, float hi) {
    uint32_t r;
    asm("cvt.rn.bf16x2.f32 %0, %1, %2;" : "=r"(r) : "f"(hi), "f"(lo));
    return r;
}
__device__ __forceinline__ void mma16(float* c, uint32_t a0, uint32_t a1, uint32_t a2,
                                      uint32_t a3, uint32_t b0, uint32_t b1) {
    asm volatile(
        "mma.sync.aligned.m16n8k16.row.col.f32.bf16.bf16.f32 "
        "{%0,%1,%2,%3}, {%4,%5,%6,%7}, {%8,%9}, {%0,%1,%2,%3};"
        : "+f"(c[0]), "+f"(c[1]), "+f"(c[2]), "+f"(c[3])
        : "r"(a0), "r"(a1), "r"(a2), "r"(a3), "r"(b0), "r"(b1));
}

// ---- gather ----
__global__ void gather_kernel(const float* __restrict__ emb, const int* __restrict__ tok,
                              float* __restrict__ out, int nrows) {
    int idx = blockIdx.x * blockDim.x + threadIdx.x;
    if (idx >= nrows * 75) return;
    int r = idx / 75, c = idx - r * 75;
    reinterpret_cast<float4*>(out)[idx] =
        reinterpret_cast<const float4*>(emb)[(size_t)tok[r] * 75 + c];
}

// ---- merged colsum ----
__global__ void colsum_kernel(const float* __restrict__ Xd, const float* __restrict__ Xq,
                              float* __restrict__ outd, float* __restrict__ outq) {
    int c = blockIdx.x, b = blockIdx.y, t = threadIdx.x;
    bool isQ = (c == NCD);
    const float* X = isQ ? Xq : Xd;
    int L = isQ ? LQ : LD;
    int rows = isQ ? LQ : (LD / NCD);
    int r0 = isQ ? 0 : c * rows;
    float* op = isQ ? (outq + (size_t)b * DIM) : (outd + ((size_t)b * NCD + c) * DIM);
    for (int d = t; d < DIM; d += blockDim.x) {
        float s = 0.f;
        for (int r = 0; r < rows; r++) {
            int row = r0 + r;
            if (row < L) s += X[((size_t)b * L + row) * DIM + d];
        }
        op[d] = s;
    }
}

// ---- bow stage2 ----
__global__ void bow2_kernel(const float* __restrict__ partS, int NC, int L,
                            const float* __restrict__ W, const float* __restrict__ bias,
                            float* __restrict__ out) {
    int b = blockIdx.x, o = threadIdx.x;
    __shared__ float ssum[DIM];
    for (int d = o; d < DIM; d += CH) {
        float s = 0.f;
        for (int c = 0; c < NC; c++) s += partS[((size_t)b * NC + c) * DIM + d];
        ssum[d] = s;
    }
    __syncthreads();
    float acc = 0.f;
    const float* wr = W + (size_t)o * DIM;
    #pragma unroll 4
    for (int d = 0; d < DIM; d++) acc += ssum[d] * wr[d];
    out[b * CH + o] = acc + (float)L * bias[o];
}

// ---- word convs: 512 threads, 256-position tiles, 5x 64-dim chunks: grid (9, B) ----
__global__ void __launch_bounds__(512) wordconv_bf16_kernel(
        const int* __restrict__ dwt, const int* __restrict__ qwt,
        const float* __restrict__ wrd_emb,
        const float* __restrict__ cuW, const float* __restrict__ cuB,
        const float* __restrict__ cbW, const float* __restrict__ cbB,
        const float* __restrict__ ctW, const float* __restrict__ ctB,
        float* __restrict__ du, float* __restrict__ qu,
        float* __restrict__ db, float* __restrict__ qb,
        float* __restrict__ dt, float* __restrict__ qt) {
    extern __shared__ uint32_t sm[];
    __shared__ int toks[258];
    int gx = blockIdx.x, n = blockIdx.y;
    int conv = gx / 3, sub = gx - conv * 3;
    int K = conv + 1;
    bool isQ = (sub == 2);
    const int* tokA = isQ ? qwt : dwt;
    int L  = isQ ? LQ : LD;
    int l0 = isQ ? 0 : sub * 256;
    const float* W   = (conv == 0) ? cuW : (conv == 1) ? cbW : ctW;
    const float* Bsv = (conv == 0) ? cuB : (conv == 1) ? cbB : ctB;
    int Lout = (conv == 0) ? (isQ ? 20 : 512) : (conv == 1) ? (isQ ? 19 : 511) : (isQ ? 18 : 510);
    float* outP = (conv == 0) ? (isQ ? qu : du) : (conv == 1) ? (isQ ? qb : db) : (isQ ? qt : dt);

    int t = threadIdx.x, w = t >> 5, lane = t & 31;
    int g = lane >> 2, tg = lane & 3;
    uint32_t* Xs = sm;
    uint32_t* Wf = sm + 258 * WXS;   // fragments: [kb][ks(4)][nt(16)][lane][slot]
    int XR = 255 + K;

    if (t < XR) toks[t] = (l0 + t < L) ? tokA[(size_t)n * L + l0 + t] : 0;
    __syncthreads();

    float acc[16][4];
    #pragma unroll
    for (int nt = 0; nt < 16; nt++)
        #pragma unroll
        for (int i = 0; i < 4; i++) acc[nt][i] = 0.f;

    for (int c = 0; c < 5; c++) {
        int d0 = c * 64;
        __syncthreads();
        // X chunk: XR rows x 32 packed words
        for (int i = t; i < XR * 32; i += 512) {
            int r = i >> 5, j = i & 31;
            int d = d0 + 2 * j;
            float2 v = make_float2(0.f, 0.f);
            if (d + 1 < DIM && l0 + r < L)
                v = *reinterpret_cast<const float2*>(&wrd_emb[(size_t)toks[r] * DIM + d]);
            Xs[r * WXS + j] = packbf(v.x, v.y);
        }
        // W chunk in fragment order
        for (int i = t; i < K * 128 * 32; i += 512) {
            int kb = i >> 12, rem = i & 4095, ch = rem >> 5, j = rem & 31;
            int d = d0 + 2 * j;
            float2 v = make_float2(0.f, 0.f);
            if (d + 1 < DIM)
                v = *reinterpret_cast<const float2*>(&W[((size_t)ch * K + kb) * DIM + d]);
            int ks = j >> 3, jj = j & 7, slot = jj >> 2, tg2 = jj & 3;
            int nt = ch >> 3, g2 = ch & 7;
            int lane2 = g2 * 4 + tg2;
            Wf[((((kb * 4 + ks) * 16 + nt) * 32 + lane2) << 1) + slot] = packbf(v.x, v.y);
        }
        __syncthreads();
        for (int kb = 0; kb < K; kb++) {
            #pragma unroll
            for (int ks = 0; ks < 4; ks++) {
                int k0 = ks * 8;
                int ar = w * 16 + g + kb;
                uint32_t a0 = Xs[ar * WXS + k0 + tg];
                uint32_t a1 = Xs[(ar + 8) * WXS + k0 + tg];
                uint32_t a2 = Xs[ar * WXS + k0 + tg + 4];
                uint32_t a3 = Xs[(ar + 8) * WXS + k0 + tg + 4];
                const uint2* fb = reinterpret_cast<const uint2*>(
                    Wf + (((kb * 4 + ks) * 16) * 32 << 1)) + lane;
                #pragma unroll
                for (int nt = 0; nt < 16; nt++) {
                    uint2 bb = fb[nt * 32];
                    mma16(acc[nt], a0, a1, a2, a3, bb.x, bb.y);
                }
            }
        }
    }

    float ssq0 = 0.f, ssq1 = 0.f;
    #pragma unroll
    for (int nt = 0; nt < 16; nt++) {
        int cA = nt * 8 + tg * 2;
        float b0v = Bsv[cA], b1v = Bsv[cA + 1];
        float v00 = fmaxf(acc[nt][0] + b0v, 0.f);
        float v01 = fmaxf(acc[nt][1] + b1v, 0.f);
        float v10 = fmaxf(acc[nt][2] + b0v, 0.f);
        float v11 = fmaxf(acc[nt][3] + b1v, 0.f);
        acc[nt][0] = v00; acc[nt][1] = v01; acc[nt][2] = v10; acc[nt][3] = v11;
        ssq0 += v00 * v00 + v01 * v01;
        ssq1 += v10 * v10 + v11 * v11;
    }
    ssq0 += __shfl_xor_sync(0xffffffffu, ssq0, 1);
    ssq0 += __shfl_xor_sync(0xffffffffu, ssq0, 2);
    ssq1 += __shfl_xor_sync(0xffffffffu, ssq1, 1);
    ssq1 += __shfl_xor_sync(0xffffffffu, ssq1, 2);
    float inv0 = 1.f / fmaxf(sqrtf(ssq0), 1e-10f);
    float inv1 = 1.f / fmaxf(sqrtf(ssq1), 1e-10f);
    int r0 = w * 16 + g, r1 = r0 + 8;
    if (l0 + r0 < Lout) {
        float* op = outP + ((size_t)n * Lout + l0 + r0) * CH;
        #pragma unroll
        for (int nt = 0; nt < 16; nt++)
            *reinterpret_cast<float2*>(op + nt * 8 + tg * 2) =
                make_float2(acc[nt][0] * inv0, acc[nt][1] * inv0);
    }
    if (l0 + r1 < Lout) {
        float* op = outP + ((size_t)n * Lout + l0 + r1) * CH;
        #pragma unroll
        for (int nt = 0; nt < 16; nt++)
            *reinterpret_cast<float2*>(op + nt * 8 + tg * 2) =
                make_float2(acc[nt][2] * inv1, acc[nt][3] * inv1);
    }
}

// ---- entity desc conv via mma.sync BF16: grid (2, B); warp = entity ----
__global__ void __launch_bounds__(256) entconv_bf16_kernel(
        const int* __restrict__ qet, const int* __restrict__ det,
        const float* __restrict__ wrd_emb,
        const float* __restrict__ cdW, const float* __restrict__ cdB,
        float* __restrict__ econvP) {
    extern __shared__ uint32_t sm[];
    __shared__ int toks_s[160];
    int tile = blockIdx.x, b = blockIdx.y;
    int t = threadIdx.x, w = t >> 5, lane = t & 31;
    int g = lane >> 2, tg = lane & 3;
    constexpr int K = WIN;
    uint32_t* Xs = sm;
    uint32_t* Ws = sm + 160 * XSTR;

    if (t < 160) {
        int e = t / DESC, p = t - e * DESC;
        int eg = tile * 8 + e;
        int id = 0;
        if (eg < EQ)        id = qet[b * (EQ * DESC) + eg * DESC + p];
        else if (eg < NENT) id = det[b * (ED * DESC) + (eg - EQ) * DESC + p];
        toks_s[t] = id;
    }
    __syncthreads();

    float acc[16][4];
    #pragma unroll
    for (int nt = 0; nt < 16; nt++)
        #pragma unroll
        for (int i = 0; i < 4; i++) acc[nt][i] = 0.f;

    for (int c = 0; c < 10; c++) {
        int d0 = c * 32;
        __syncthreads();
        for (int i = t; i < 160 * 16; i += 256) {
            int r = i >> 4, j = i & 15;
            int d = d0 + 2 * j;
            float2 v = make_float2(0.f, 0.f);
            if (d + 1 < DIM)
                v = *reinterpret_cast<const float2*>(&wrd_emb[(size_t)toks_s[r] * DIM + d]);
            Xs[r * XSTR + j] = packbf(v.x, v.y);
        }
        for (int i = t; i < K * 128 * 16; i += 256) {
            int kb = i >> 11, rem = i & 2047, ch = rem >> 4, j = rem & 15;
            int d = d0 + 2 * j;
            float2 v = make_float2(0.f, 0.f);
            if (d + 1 < DIM)
                v = *reinterpret_cast<const float2*>(&cdW[((size_t)ch * K + kb) * DIM + d]);
            Ws[kb * (128 * XSTR) + ch * XSTR + j] = packbf(v.x, v.y);
        }
        __syncthreads();
        for (int kb = 0; kb < K; kb++) {
            const uint32_t* Wb = Ws + kb * (128 * XSTR);
            #pragma unroll
            for (int ks = 0; ks < 2; ks++) {
                int k0 = ks * 8;
                int xr = w * 20 + g + kb;
                uint32_t a0 = Xs[xr * XSTR + k0 + tg];
                uint32_t a1 = Xs[(xr + 8) * XSTR + k0 + tg];
                uint32_t a2 = Xs[xr * XSTR + k0 + tg + 4];
                uint32_t a3 = Xs[(xr + 8) * XSTR + k0 + tg + 4];
                #pragma unroll
                for (int nt = 0; nt < 16; nt++) {
                    int bch = nt * 8 + g;
                    uint32_t b0 = Wb[bch * XSTR + k0 + tg];
                    uint32_t b1 = Wb[bch * XSTR + k0 + tg + 4];
                    mma16(acc[nt], a0, a1, a2, a3, b0, b1);
                }
            }
        }
    }

    int eg = tile * 8 + w;
    #pragma unroll
    for (int nt = 0; nt < 16; nt++) {
        int cA = nt * 8 + tg * 2;
        float b0v = cdB[cA], b1v = cdB[cA + 1];
        float m0 = fmaxf(fmaxf(acc[nt][0] + b0v, 0.f), fmaxf(acc[nt][2] + b0v, 0.f));
        float m1 = fmaxf(fmaxf(acc[nt][1] + b1v, 0.f), fmaxf(acc[nt][3] + b1v, 0.f));
        #pragma unroll
        for (int off = 4; off < 32; off <<= 1) {
            m0 = fmaxf(m0, __shfl_xor_sync(0xffffffffu, m0, off));
            m1 = fmaxf(m1, __shfl_xor_sync(0xffffffffu, m1, off));
        }
        if (lane < 4 && eg < NENT) {
            float* op = econvP + ((size_t)b * NENT + eg) * CH;
            op[cA] = m0; op[cA + 1] = m1;
        }
    }
}

// ---- entity post ----
__global__ void __launch_bounds__(128) entity_post_kernel(
        const int* __restrict__ qei, const int* __restrict__ qew, const float* __restrict__ qbow,
        const int* __restrict__ dei, const int* __restrict__ dew, const float* __restrict__ dbow,
        const float* __restrict__ ent_emb, const float* __restrict__ car_emb,
        const float* __restrict__ econvP,
        float* __restrict__ qs_out, float* __restrict__ ds_out) {
    __shared__ int crows[KC];
    __shared__ float bv[CH];
    __shared__ float logits[KC];
    __shared__ float att[KC];
    __shared__ float red[4];
    int eg = blockIdx.x, b = blockIdx.y;
    bool isQ = (eg < EQ);
    int e = isQ ? eg : eg - EQ;
    int n_ent = isQ ? EQ : ED;
    const int* ids_e   = isQ ? qei : dei;
    const int* ids_car = isQ ? qew : dew;
    const float* bow   = isQ ? qbow : dbow;
    float* out         = isQ ? qs_out : ds_out;
    int o = threadIdx.x, warp = o >> 5, lane = o & 31;

    if (o < KC) crows[o] = ids_car[(size_t)b * n_ent * KC + e * KC + o];
    bv[o] = bow[b * CH + o];
    __syncthreads();
    if (o < KC) {
        const float* cr = car_emb + (size_t)crows[o] * CH;
        float s = 0.f;
        #pragma unroll 4
        for (int c = 0; c < CH; c++) s += bv[c] * cr[c];
        logits[o] = s;
    }
    __syncthreads();
    if (o == 0) {
        float mx = -1e30f;
        #pragma unroll
        for (int k = 0; k < KC; k++) mx = fmaxf(mx, logits[k]);
        float ssum = 0.f;
        #pragma unroll
        for (int k = 0; k < KC; k++) { float ev = __expf(logits[k] - mx); att[k] = ev; ssum += ev; }
        float inv = 1.f / ssum;
        #pragma unroll
        for (int k = 0; k < KC; k++) att[k] *= inv;
    }
    __syncthreads();
    float ew = 0.f;
    #pragma unroll
    for (int k = 0; k < KC; k++) ew += att[k] * car_emb[(size_t)crows[k] * CH + o];
    float v = ent_emb[(size_t)ids_e[b * n_ent + e] * CH + o]
            + econvP[((size_t)b * NENT + eg) * CH + o] + ew;
    float ss = v * v;
    #pragma unroll
    for (int off = 16; off > 0; off >>= 1) ss += __shfl_xor_sync(0xffffffffu, ss, off);
    if (lane == 0) red[warp] = ss;
    __syncthreads();
    float tot = red[0] + red[1] + red[2] + red[3];
    float inv = 1.f / fmaxf(sqrtf(tot), 1e-10f);
    out[((size_t)b * n_ent + e) * CH + o] = v * inv;
}

// ---- fused pooling, 2 q-rows per thread ----
__global__ void __launch_bounds__(128) pool_all_kernel(
        const float* __restrict__ Qu, const float* __restrict__ Qb,
        const float* __restrict__ Qt, const float* __restrict__ Qs,
        const float* __restrict__ Du, const float* __restrict__ Db,
        const float* __restrict__ Dt, const float* __restrict__ Dsm,
        const float* __restrict__ dwm, const float* __restrict__ dem,
        float* __restrict__ part) {
    int slot = blockIdx.x, b = blockIdx.y;
    int dm = slot >> 2, chunk = slot & 3;
    const float* D  = (dm == 0) ? Du : (dm == 1) ? Db : (dm == 2) ? Dt : Dsm;
    int Ld          = (dm == 0) ? 512 : (dm == 1) ? 511 : (dm == 2) ? 510 : 10;
    const float* md = (dm < 3) ? dwm : dem;
    int md_stride   = (dm < 3) ? 512 : 10;
    int chunkRows   = (dm < 3) ? 128 : 16;
    int t = threadIdx.x, p = t >> 2, g = t & 3;

    auto qrow = [&](int qr) -> const float* {
        if (qr < 20)      return Qu + (size_t)(b * 20 + qr) * CH;
        else if (qr < 39) return Qb + (size_t)(b * 19 + (qr - 20)) * CH;
        else if (qr < 57) return Qt + (size_t)(b * 18 + (qr - 39)) * CH;
        else if (qr < 62) return Qs + (size_t)(b * 5 + (qr - 57)) * CH;
        return nullptr;
    };
    float4 q0[8], q1[8];
    {
        const float* p0 = qrow(p);
        const float* p1 = qrow(p + 32);
        #pragma unroll
        for (int i = 0; i < 8; i++) {
            q0[i] = p0 ? reinterpret_cast<const float4*>(p0)[g + 4 * i]
                       : make_float4(0.f, 0.f, 0.f, 0.f);
            q1[i] = p1 ? reinterpret_cast<const float4*>(p1)[g + 4 * i]
                       : make_float4(0.f, 0.f, 0.f, 0.f);
        }
    }

    float mu0 = c_mu[g],     ni0 = c_nis[g];
    float mu1 = c_mu[g + 4], ni1 = c_nis[g + 4];
    float mu2 = 0.f, ni2 = 0.f;
    bool has2 = (g + 8) < NB;
    if (has2) { mu2 = c_mu[g + 8]; ni2 = c_nis[g + 8]; }

    float a00 = 0.f, a01 = 0.f, a02 = 0.f;
    float a10 = 0.f, a11 = 0.f, a12 = 0.f;
    __shared__ alignas(16) float Ds[16][CH];
    __shared__ float msk[16];

    int ld_begin = chunk * chunkRows;
    for (int ld0 = ld_begin; ld0 < ld_begin + chunkRows; ld0 += 16) {
        __syncthreads();
        #pragma unroll
        for (int i = t; i < 512; i += 128) {
            int r = i >> 5, c = i & 31;
            int row = ld0 + r;
            float4 v = make_float4(0.f, 0.f, 0.f, 0.f);
            if (row < Ld)
                v = reinterpret_cast<const float4*>(D + ((size_t)b * Ld + row) * CH)[c];
            reinterpret_cast<float4*>(&Ds[r][0])[c] = v;
        }
        if (t < 16) {
            int rr = ld0 + t;
            msk[t] = (rr < Ld) ? md[(size_t)b * md_stride + rr] : 0.f;
        }
        __syncthreads();
        #pragma unroll
        for (int r = 0; r < 16; r++) {
            const float4* dp = reinterpret_cast<const float4*>(&Ds[r][0]);
            float s0 = 0.f, s1 = 0.f;
            #pragma unroll
            for (int i = 0; i < 8; i++) {
                float4 d4 = dp[g + 4 * i];
                s0 += d4.x * q0[i].x + d4.y * q0[i].y + d4.z * q0[i].z + d4.w * q0[i].w;
                s1 += d4.x * q1[i].x + d4.y * q1[i].y + d4.z * q1[i].z + d4.w * q1[i].w;
            }
            s0 += __shfl_xor_sync(0xffffffffu, s0, 1);
            s0 += __shfl_xor_sync(0xffffffffu, s0, 2);
            s1 += __shfl_xor_sync(0xffffffffu, s1, 1);
            s1 += __shfl_xor_sync(0xffffffffu, s1, 2);
            float m = msk[r];
            float e0, e1;
            e0 = (s0 - mu0) * (s0 - mu0) * ni0;
            e1 = (s1 - mu0) * (s1 - mu0) * ni0;
            if (e0 > -60.f) a00 += m * __expf(e0);
            if (e1 > -60.f) a10 += m * __expf(e1);
            e0 = (s0 - mu1) * (s0 - mu1) * ni1;
            e1 = (s1 - mu1) * (s1 - mu1) * ni1;
            if (e0 > -60.f) a01 += m * __expf(e0);
            if (e1 > -60.f) a11 += m * __expf(e1);
            if (has2) {
                e0 = (s0 - mu2) * (s0 - mu2) * ni2;
                e1 = (s1 - mu2) * (s1 - mu2) * ni2;
                if (e0 > -60.f) a02 += m * __expf(e0);
                if (e1 > -60.f) a12 += m * __expf(e1);
            }
        }
    }
    size_t base0 = ((size_t)slot * BB + b) * (QR_TOT * NB) + (size_t)p * NB;
    size_t base1 = ((size_t)slot * BB + b) * (QR_TOT * NB) + (size_t)(p + 32) * NB;
    part[base0 + g]     = a00;
    part[base0 + g + 4] = a01;
    if (has2) part[base0 + g + 8] = a02;
    part[base1 + g]     = a10;
    part[base1 + g + 4] = a11;
    if (has2) part[base1 + g + 8] = a12;
}

// ---- final ----
__global__ void __launch_bounds__(256) final_kernel(
        const float* __restrict__ part, const float* __restrict__ qwm,
        const float* __restrict__ qem, const float* __restrict__ dW,
        const float* __restrict__ dB, float* __restrict__ out) {
    int b = blockIdx.x, t = threadIdx.x;
    float local = 0.f;
    for (int p = 0; p < NPAIR; p++) {
        int qsrc = c_pq[p], dmat = c_pd[p];
        int Lqp = c_qlen[qsrc], off = c_qoff[qsrc];
        int slot = c_dslot[dmat], nch = c_dnch[dmat];
        int tot = Lqp * NB;
        for (int idx = t; idx < tot; idx += 256) {
            int lq = idx / NB, k = idx - lq * NB;
            int row = off + lq;
            float s = 0.f;
            for (int c = 0; c < nch; c++)
                s += part[((size_t)(slot + c) * BB + b) * (QR_TOT * NB) + row * NB + k];
            float mq = (qsrc < 3) ? qwm[b * 20 + lq] : qem[b * 5 + lq];
            local += dW[p * NB + k] * (__logf(fmaxf(s, 1e-10f)) * 0.01f * mq);
        }
    }
    #pragma unroll
    for (int off = 16; off > 0; off >>= 1) local += __shfl_xor_sync(0xffffffffu, local, off);
    __shared__ float r8[8];
    if ((t & 31) == 0) r8[t >> 5] = local;
    __syncthreads();
    if (t == 0) {
        float s = 0.f;
        #pragma unroll
        for (int w = 0; w < 8; w++) s += r8[w];
        out[b] = tanhf(s + dB[0]);
    }
}

// ---- launcher ----
extern "C" void kernel_launch(void* const* d_in, const int* in_sizes, int n_in,
                              void* d_out, int out_size) {
    const int*   qwt = (const int*)d_in[0];
    const float* qwm = (const float*)d_in[1];
    const int*   qei = (const int*)d_in[2];
    const int*   qet = (const int*)d_in[3];
    const int*   qew = (const int*)d_in[4];
    const float* qem = (const float*)d_in[5];
    const int*   dwt = (const int*)d_in[6];
    const float* dwm = (const float*)d_in[7];
    const int*   dei = (const int*)d_in[8];
    const int*   det = (const int*)d_in[9];
    const int*   dew = (const int*)d_in[10];
    const float* dem = (const float*)d_in[11];
    const float* wrd = (const float*)d_in[12];
    const float* ent = (const float*)d_in[13];
    const float* car = (const float*)d_in[14];
    const float* bowW = (const float*)d_in[15];
    const float* bowB = (const float*)d_in[16];
    const float* cuW = (const float*)d_in[17];
    const float* cuB = (const float*)d_in[18];
    const float* cbW = (const float*)d_in[19];
    const float* cbB = (const float*)d_in[20];
    const float* ctW = (const float*)d_in[21];
    const float* ctB = (const float*)d_in[22];
    const float* cdW = (const float*)d_in[23];
    const float* cdB = (const float*)d_in[24];
    const float* dfW = (const float*)d_in[25];
    const float* dfB = (const float*)d_in[26];
    float* out = (float*)d_out;

    float* S = nullptr;
    cudaGetSymbolAddress((void**)&S, g_scratch);
    float* qw    = S + OFF_QW;
    float* dw    = S + OFF_DW;
    float* qbow  = S + OFF_QBOW;
    float* dbow  = S + OFF_DBOW;
    float* qu    = S + OFF_QU;
    float* qb    = S + OFF_QB;
    float* qt    = S + OFF_QT;
    float* du    = S + OFF_DU;
    float* db    = S + OFF_DB;
    float* dt    = S + OFF_DT;
    float* qs    = S + OFF_QS;
    float* ds    = S + OFF_DS;
    float* cs1   = S + OFF_CS1;
    float* cs8   = S + OFF_CS8;
    float* econ  = S + OFF_ECONV;
    float* partP = S + OFF_PART;

    static cudaStream_t sA = nullptr, sB = nullptr;
    static cudaEvent_t evF = nullptr, evB = nullptr, evA = nullptr;
    if (sA == nullptr) {
        cudaStreamCreateWithFlags(&sA, cudaStreamNonBlocking);
        cudaStreamCreateWithFlags(&sB, cudaStreamNonBlocking);
        cudaEventCreateWithFlags(&evF, cudaEventDisableTiming);
        cudaEventCreateWithFlags(&evB, cudaEventDisableTiming);
        cudaEventCreateWithFlags(&evA, cudaEventDisableTiming);
        cudaFuncSetAttribute(wordconv_bf16_kernel,
                             cudaFuncAttributeMaxDynamicSharedMemorySize, WORD_SMEM);
        cudaFuncSetAttribute(entconv_bf16_kernel,
                             cudaFuncAttributeMaxDynamicSharedMemorySize, ENT_SMEM);
    }

    // FORK from capture-origin stream
    cudaEventRecord(evF, 0);
    cudaStreamWaitEvent(sA, evF, 0);
    cudaStreamWaitEvent(sB, evF, 0);

    // submissions #1-#3: side streams
    entconv_bf16_kernel<<<dim3(2, BB), 256, ENT_SMEM, sA>>>(qet, det, wrd, cdW, cdB, econ);
    gather_kernel<<<(BB * LQ * 75 + 255) / 256, 256, 0, sB>>>(wrd, qwt, qw, BB * LQ);
    gather_kernel<<<(BB * LD * 75 + 255) / 256, 256, 0, sB>>>(wrd, dwt, dw, BB * LD);
    // submission #4 (PROFILED): 512-thread BF16 word convs on main
    wordconv_bf16_kernel<<<dim3(9, BB), 512, WORD_SMEM>>>(dwt, qwt, wrd,
                                                          cuW, cuB, cbW, cbB, ctW, ctB,
                                                          du, qu, db, qb, dt, qt);
    // stream B continues
    colsum_kernel<<<dim3(NCD + 1, BB), 128, 0, sB>>>(dw, qw, cs8, cs1);
    bow2_kernel<<<BB, 128, 0, sB>>>(cs1, 1, LQ, bowW, bowB, qbow);
    bow2_kernel<<<BB, 128, 0, sB>>>(cs8, NCD, LD, bowW, bowB, dbow);
    cudaEventRecord(evB, sB);
    cudaStreamWaitEvent(sA, evB, 0);
    entity_post_kernel<<<dim3(EQ + ED, BB), 128, 0, sA>>>(qei, qew, qbow, dei, dew, dbow,
                                                          ent, car, econ, qs, ds);
    // JOIN A into main
    cudaEventRecord(evA, sA);
    cudaStreamWaitEvent(0, evA, 0);

    pool_all_kernel<<<dim3(PSLOTS, BB), 128>>>(qu, qb, qt, qs, du, db, dt, ds,
                                               dwm, dem, partP);
    final_kernel<<<BB, 256>>>(partP, qwm, qem, dfW, dfB, out);
}

// round 16
// speedup vs baseline: 1.0991x; 1.0991x over previous
#include <cuda_runtime.h>
#include <cstdint>
#include <math.h>

constexpr int BB = 64, LQ = 20, LD = 512, DIM = 300, NB = 11, WIN = 5;
constexpr int EQ = 5, ED = 10, DESC = 20, KC = 10;
constexpr int CH = 128, NPAIR = 16, QR_TOT = 64, PSLOTS = 13, NCD = 16, NENT = 15;
constexpr int XSTR = 20;

__constant__ float c_mu[NB]  = {1.0f, 0.9f, 0.7f, 0.5f, 0.3f, 0.1f, -0.1f, -0.3f, -0.5f, -0.7f, -0.9f};
__constant__ float c_nis[NB] = {-500000.0f, -50.0f, -50.0f, -50.0f, -50.0f, -50.0f, -50.0f, -50.0f, -50.0f, -50.0f, -50.0f};
__constant__ int c_pq[NPAIR] = {0,0,0,1,2,1,1,2,2,3,3,3,0,1,2,3};
__constant__ int c_pd[NPAIR] = {0,2,1,0,0,1,2,1,2,0,1,2,3,3,3,3};
__constant__ int c_qoff[4] = {0,20,39,57};
__constant__ int c_qlen[4] = {20,19,18,5};
__constant__ int c_dslot[4] = {0,4,8,12};
__constant__ int c_dnch[4] = {4,4,4,1};

constexpr size_t OFF_QW    = 0;
constexpr size_t OFF_DW    = OFF_QW    + (size_t)BB*LQ*DIM;
constexpr size_t OFF_QBOW  = OFF_DW    + (size_t)BB*LD*DIM;
constexpr size_t OFF_DBOW  = OFF_QBOW  + (size_t)BB*CH;
constexpr size_t OFF_QU    = OFF_DBOW  + (size_t)BB*CH;
constexpr size_t OFF_QB    = OFF_QU    + (size_t)BB*20*CH;
constexpr size_t OFF_QT    = OFF_QB    + (size_t)BB*19*CH;
constexpr size_t OFF_DU    = OFF_QT    + (size_t)BB*18*CH;
constexpr size_t OFF_DB    = OFF_DU    + (size_t)BB*512*CH;
constexpr size_t OFF_DT    = OFF_DB    + (size_t)BB*511*CH;
constexpr size_t OFF_QS    = OFF_DT    + (size_t)BB*510*CH;
constexpr size_t OFF_DS    = OFF_QS    + (size_t)BB*EQ*CH;
constexpr size_t OFF_CS1   = OFF_DS    + (size_t)BB*ED*CH;
constexpr size_t OFF_CS8   = OFF_CS1   + (size_t)BB*DIM;
constexpr size_t OFF_ECONV = OFF_CS8   + (size_t)BB*NCD*DIM;
constexpr size_t OFF_PART  = OFF_ECONV + (size_t)BB*NENT*CH;
constexpr size_t SCRATCH_TOTAL = OFF_PART + (size_t)PSLOTS*BB*QR_TOT*NB;
__device__ float g_scratch[SCRATCH_TOTAL];

constexpr int WORD_SMEM = (132*XSTR + 3*128*XSTR) * 4;
constexpr int ENT_SMEM  = (160*XSTR + 5*128*XSTR) * 4;

__device__ __forceinline__ uint32_t packbf(float lo, float hi) {
    uint32_t r;
    asm("cvt.rn.bf16x2.f32 %0, %1, %2;" : "=r"(r) : "f"(hi), "f"(lo));
    return r;
}
__device__ __forceinline__ void mma16(float* c, uint32_t a0, uint32_t a1, uint32_t a2,
                                      uint32_t a3, uint32_t b0, uint32_t b1) {
    asm volatile(
        "mma.sync.aligned.m16n8k16.row.col.f32.bf16.bf16.f32 "
        "{%0,%1,%2,%3}, {%4,%5,%6,%7}, {%8,%9}, {%0,%1,%2,%3};"
        : "+f"(c[0]), "+f"(c[1]), "+f"(c[2]), "+f"(c[3])
        : "r"(a0), "r"(a1), "r"(a2), "r"(a3), "r"(b0), "r"(b1));
}

// ---- gather ----
__global__ void gather_kernel(const float* __restrict__ emb, const int* __restrict__ tok,
                              float* __restrict__ out, int nrows) {
    int idx = blockIdx.x * blockDim.x + threadIdx.x;
    if (idx >= nrows * 75) return;
    int r = idx / 75, c = idx - r * 75;
    reinterpret_cast<float4*>(out)[idx] =
        reinterpret_cast<const float4*>(emb)[(size_t)tok[r] * 75 + c];
}

// ---- merged colsum ----
__global__ void colsum_kernel(const float* __restrict__ Xd, const float* __restrict__ Xq,
                              float* __restrict__ outd, float* __restrict__ outq) {
    int c = blockIdx.x, b = blockIdx.y, t = threadIdx.x;
    bool isQ = (c == NCD);
    const float* X = isQ ? Xq : Xd;
    int L = isQ ? LQ : LD;
    int rows = isQ ? LQ : (LD / NCD);
    int r0 = isQ ? 0 : c * rows;
    float* op = isQ ? (outq + (size_t)b * DIM) : (outd + ((size_t)b * NCD + c) * DIM);
    for (int d = t; d < DIM; d += blockDim.x) {
        float s = 0.f;
        for (int r = 0; r < rows; r++) {
            int row = r0 + r;
            if (row < L) s += X[((size_t)b * L + row) * DIM + d];
        }
        op[d] = s;
    }
}

// ---- bow stage2 ----
__global__ void bow2_kernel(const float* __restrict__ partS, int NC, int L,
                            const float* __restrict__ W, const float* __restrict__ bias,
                            float* __restrict__ out) {
    int b = blockIdx.x, o = threadIdx.x;
    __shared__ float ssum[DIM];
    for (int d = o; d < DIM; d += CH) {
        float s = 0.f;
        for (int c = 0; c < NC; c++) s += partS[((size_t)b * NC + c) * DIM + d];
        ssum[d] = s;
    }
    __syncthreads();
    float acc = 0.f;
    const float* wr = W + (size_t)o * DIM;
    #pragma unroll 4
    for (int d = 0; d < DIM; d++) acc += ssum[d] * wr[d];
    out[b * CH + o] = acc + (float)L * bias[o];
}

// ---- word convs via mma.sync BF16 k16 (round-12 best version): grid (15, B) ----
__global__ void __launch_bounds__(256) wordconv_bf16_kernel(
        const int* __restrict__ dwt, const int* __restrict__ qwt,
        const float* __restrict__ wrd_emb,
        const float* __restrict__ cuW, const float* __restrict__ cuB,
        const float* __restrict__ cbW, const float* __restrict__ cbB,
        const float* __restrict__ ctW, const float* __restrict__ ctB,
        float* __restrict__ du, float* __restrict__ qu,
        float* __restrict__ db, float* __restrict__ qb,
        float* __restrict__ dt, float* __restrict__ qt) {
    extern __shared__ uint32_t sm[];
    __shared__ int toks[132];
    int gx = blockIdx.x, n = blockIdx.y;
    int conv = gx / 5, tile = gx - conv * 5;
    int K = conv + 1;
    bool isQ = (tile == 4);
    const int* tokA = isQ ? qwt : dwt;
    int L  = isQ ? LQ : LD;
    int l0 = isQ ? 0 : tile * 128;
    const float* W   = (conv == 0) ? cuW : (conv == 1) ? cbW : ctW;
    const float* Bsv = (conv == 0) ? cuB : (conv == 1) ? cbB : ctB;
    int Lout = (conv == 0) ? (isQ ? 20 : 512) : (conv == 1) ? (isQ ? 19 : 511) : (isQ ? 18 : 510);
    float* outP = (conv == 0) ? (isQ ? qu : du) : (conv == 1) ? (isQ ? qb : db) : (isQ ? qt : dt);

    int t = threadIdx.x, w = t >> 5, lane = t & 31;
    int g = lane >> 2, tg = lane & 3;
    uint32_t* Xs = sm;
    uint32_t* Ws = sm + 132 * XSTR;
    int XR = 127 + K;

    if (t < XR) toks[t] = (l0 + t < L) ? tokA[(size_t)n * L + l0 + t] : 0;
    __syncthreads();

    float acc[16][4];
    #pragma unroll
    for (int nt = 0; nt < 16; nt++)
        #pragma unroll
        for (int i = 0; i < 4; i++) acc[nt][i] = 0.f;

    for (int c = 0; c < 10; c++) {
        int d0 = c * 32;
        __syncthreads();
        for (int i = t; i < XR * 16; i += 256) {
            int r = i >> 4, j = i & 15;
            int d = d0 + 2 * j;
            float2 v = make_float2(0.f, 0.f);
            if (d + 1 < DIM && l0 + r < L)
                v = *reinterpret_cast<const float2*>(&wrd_emb[(size_t)toks[r] * DIM + d]);
            Xs[r * XSTR + j] = packbf(v.x, v.y);
        }
        for (int i = t; i < K * 128 * 16; i += 256) {
            int kb = i >> 11, rem = i & 2047, ch = rem >> 4, j = rem & 15;
            int d = d0 + 2 * j;
            float2 v = make_float2(0.f, 0.f);
            if (d + 1 < DIM)
                v = *reinterpret_cast<const float2*>(&W[((size_t)ch * K + kb) * DIM + d]);
            Ws[kb * (128 * XSTR) + ch * XSTR + j] = packbf(v.x, v.y);
        }
        __syncthreads();
        for (int kb = 0; kb < K; kb++) {
            const uint32_t* Wb = Ws + kb * (128 * XSTR);
            #pragma unroll
            for (int ks = 0; ks < 2; ks++) {
                int k0 = ks * 8;
                int ar = w * 16 + g + kb;
                uint32_t a0 = Xs[ar * XSTR + k0 + tg];
                uint32_t a1 = Xs[(ar + 8) * XSTR + k0 + tg];
                uint32_t a2 = Xs[ar * XSTR + k0 + tg + 4];
                uint32_t a3 = Xs[(ar + 8) * XSTR + k0 + tg + 4];
                #pragma unroll
                for (int nt = 0; nt < 16; nt++) {
                    int bch = nt * 8 + g;
                    uint32_t b0 = Wb[bch * XSTR + k0 + tg];
                    uint32_t b1 = Wb[bch * XSTR + k0 + tg + 4];
                    mma16(acc[nt], a0, a1, a2, a3, b0, b1);
                }
            }
        }
    }

    float ssq0 = 0.f, ssq1 = 0.f;
    #pragma unroll
    for (int nt = 0; nt < 16; nt++) {
        int cA = nt * 8 + tg * 2;
        float b0v = Bsv[cA], b1v = Bsv[cA + 1];
        float v00 = fmaxf(acc[nt][0] + b0v, 0.f);
        float v01 = fmaxf(acc[nt][1] + b1v, 0.f);
        float v10 = fmaxf(acc[nt][2] + b0v, 0.f);
        float v11 = fmaxf(acc[nt][3] + b1v, 0.f);
        acc[nt][0] = v00; acc[nt][1] = v01; acc[nt][2] = v10; acc[nt][3] = v11;
        ssq0 += v00 * v00 + v01 * v01;
        ssq1 += v10 * v10 + v11 * v11;
    }
    ssq0 += __shfl_xor_sync(0xffffffffu, ssq0, 1);
    ssq0 += __shfl_xor_sync(0xffffffffu, ssq0, 2);
    ssq1 += __shfl_xor_sync(0xffffffffu, ssq1, 1);
    ssq1 += __shfl_xor_sync(0xffffffffu, ssq1, 2);
    float inv0 = 1.f / fmaxf(sqrtf(ssq0), 1e-10f);
    float inv1 = 1.f / fmaxf(sqrtf(ssq1), 1e-10f);
    int r0 = w * 16 + g, r1 = r0 + 8;
    if (l0 + r0 < Lout) {
        float* op = outP + ((size_t)n * Lout + l0 + r0) * CH;
        #pragma unroll
        for (int nt = 0; nt < 16; nt++)
            *reinterpret_cast<float2*>(op + nt * 8 + tg * 2) =
                make_float2(acc[nt][0] * inv0, acc[nt][1] * inv0);
    }
    if (l0 + r1 < Lout) {
        float* op = outP + ((size_t)n * Lout + l0 + r1) * CH;
        #pragma unroll
        for (int nt = 0; nt < 16; nt++)
            *reinterpret_cast<float2*>(op + nt * 8 + tg * 2) =
                make_float2(acc[nt][2] * inv1, acc[nt][3] * inv1);
    }
}

// ---- entity desc conv via mma.sync BF16: grid (2, B); warp = entity ----
__global__ void __launch_bounds__(256) entconv_bf16_kernel(
        const int* __restrict__ qet, const int* __restrict__ det,
        const float* __restrict__ wrd_emb,
        const float* __restrict__ cdW, const float* __restrict__ cdB,
        float* __restrict__ econvP) {
    extern __shared__ uint32_t sm[];
    __shared__ int toks_s[160];
    int tile = blockIdx.x, b = blockIdx.y;
    int t = threadIdx.x, w = t >> 5, lane = t & 31;
    int g = lane >> 2, tg = lane & 3;
    constexpr int K = WIN;
    uint32_t* Xs = sm;
    uint32_t* Ws = sm + 160 * XSTR;

    if (t < 160) {
        int e = t / DESC, p = t - e * DESC;
        int eg = tile * 8 + e;
        int id = 0;
        if (eg < EQ)        id = qet[b * (EQ * DESC) + eg * DESC + p];
        else if (eg < NENT) id = det[b * (ED * DESC) + (eg - EQ) * DESC + p];
        toks_s[t] = id;
    }
    __syncthreads();

    float acc[16][4];
    #pragma unroll
    for (int nt = 0; nt < 16; nt++)
        #pragma unroll
        for (int i = 0; i < 4; i++) acc[nt][i] = 0.f;

    for (int c = 0; c < 10; c++) {
        int d0 = c * 32;
        __syncthreads();
        for (int i = t; i < 160 * 16; i += 256) {
            int r = i >> 4, j = i & 15;
            int d = d0 + 2 * j;
            float2 v = make_float2(0.f, 0.f);
            if (d + 1 < DIM)
                v = *reinterpret_cast<const float2*>(&wrd_emb[(size_t)toks_s[r] * DIM + d]);
            Xs[r * XSTR + j] = packbf(v.x, v.y);
        }
        for (int i = t; i < K * 128 * 16; i += 256) {
            int kb = i >> 11, rem = i & 2047, ch = rem >> 4, j = rem & 15;
            int d = d0 + 2 * j;
            float2 v = make_float2(0.f, 0.f);
            if (d + 1 < DIM)
                v = *reinterpret_cast<const float2*>(&cdW[((size_t)ch * K + kb) * DIM + d]);
            Ws[kb * (128 * XSTR) + ch * XSTR + j] = packbf(v.x, v.y);
        }
        __syncthreads();
        for (int kb = 0; kb < K; kb++) {
            const uint32_t* Wb = Ws + kb * (128 * XSTR);
            #pragma unroll
            for (int ks = 0; ks < 2; ks++) {
                int k0 = ks * 8;
                int xr = w * 20 + g + kb;
                uint32_t a0 = Xs[xr * XSTR + k0 + tg];
                uint32_t a1 = Xs[(xr + 8) * XSTR + k0 + tg];
                uint32_t a2 = Xs[xr * XSTR + k0 + tg + 4];
                uint32_t a3 = Xs[(xr + 8) * XSTR + k0 + tg + 4];
                #pragma unroll
                for (int nt = 0; nt < 16; nt++) {
                    int bch = nt * 8 + g;
                    uint32_t b0 = Wb[bch * XSTR + k0 + tg];
                    uint32_t b1 = Wb[bch * XSTR + k0 + tg + 4];
                    mma16(acc[nt], a0, a1, a2, a3, b0, b1);
                }
            }
        }
    }

    int eg = tile * 8 + w;
    #pragma unroll
    for (int nt = 0; nt < 16; nt++) {
        int cA = nt * 8 + tg * 2;
        float b0v = cdB[cA], b1v = cdB[cA + 1];
        float m0 = fmaxf(fmaxf(acc[nt][0] + b0v, 0.f), fmaxf(acc[nt][2] + b0v, 0.f));
        float m1 = fmaxf(fmaxf(acc[nt][1] + b1v, 0.f), fmaxf(acc[nt][3] + b1v, 0.f));
        #pragma unroll
        for (int off = 4; off < 32; off <<= 1) {
            m0 = fmaxf(m0, __shfl_xor_sync(0xffffffffu, m0, off));
            m1 = fmaxf(m1, __shfl_xor_sync(0xffffffffu, m1, off));
        }
        if (lane < 4 && eg < NENT) {
            float* op = econvP + ((size_t)b * NENT + eg) * CH;
            op[cA] = m0; op[cA + 1] = m1;
        }
    }
}

// ---- entity post ----
__global__ void __launch_bounds__(128) entity_post_kernel(
        const int* __restrict__ qei, const int* __restrict__ qew, const float* __restrict__ qbow,
        const int* __restrict__ dei, const int* __restrict__ dew, const float* __restrict__ dbow,
        const float* __restrict__ ent_emb, const float* __restrict__ car_emb,
        const float* __restrict__ econvP,
        float* __restrict__ qs_out, float* __restrict__ ds_out) {
    __shared__ int crows[KC];
    __shared__ float bv[CH];
    __shared__ float logits[KC];
    __shared__ float att[KC];
    __shared__ float red[4];
    int eg = blockIdx.x, b = blockIdx.y;
    bool isQ = (eg < EQ);
    int e = isQ ? eg : eg - EQ;
    int n_ent = isQ ? EQ : ED;
    const int* ids_e   = isQ ? qei : dei;
    const int* ids_car = isQ ? qew : dew;
    const float* bow   = isQ ? qbow : dbow;
    float* out         = isQ ? qs_out : ds_out;
    int o = threadIdx.x, warp = o >> 5, lane = o & 31;

    if (o < KC) crows[o] = ids_car[(size_t)b * n_ent * KC + e * KC + o];
    bv[o] = bow[b * CH + o];
    __syncthreads();
    if (o < KC) {
        const float* cr = car_emb + (size_t)crows[o] * CH;
        float s = 0.f;
        #pragma unroll 4
        for (int c = 0; c < CH; c++) s += bv[c] * cr[c];
        logits[o] = s;
    }
    __syncthreads();
    if (o == 0) {
        float mx = -1e30f;
        #pragma unroll
        for (int k = 0; k < KC; k++) mx = fmaxf(mx, logits[k]);
        float ssum = 0.f;
        #pragma unroll
        for (int k = 0; k < KC; k++) { float ev = __expf(logits[k] - mx); att[k] = ev; ssum += ev; }
        float inv = 1.f / ssum;
        #pragma unroll
        for (int k = 0; k < KC; k++) att[k] *= inv;
    }
    __syncthreads();
    float ew = 0.f;
    #pragma unroll
    for (int k = 0; k < KC; k++) ew += att[k] * car_emb[(size_t)crows[k] * CH + o];
    float v = ent_emb[(size_t)ids_e[b * n_ent + e] * CH + o]
            + econvP[((size_t)b * NENT + eg) * CH + o] + ew;
    float ss = v * v;
    #pragma unroll
    for (int off = 16; off > 0; off >>= 1) ss += __shfl_xor_sync(0xffffffffu, ss, off);
    if (lane == 0) red[warp] = ss;
    __syncthreads();
    float tot = red[0] + red[1] + red[2] + red[3];
    float inv = 1.f / fmaxf(sqrtf(tot), 1e-10f);
    out[((size_t)b * n_ent + e) * CH + o] = v * inv;
}

// ---- fused pooling with telescoping Gaussian chain ----
// 256 threads: qr = t>>2 (q row), g = t&3 (dim quarter). D rows in groups of 4;
// lane g owns the chain for row (base+g); 11 accumulators per lane, cross-lane
// summed at the end.
__global__ void __launch_bounds__(256) pool_all_kernel(
        const float* __restrict__ Qu, const float* __restrict__ Qb,
        const float* __restrict__ Qt, const float* __restrict__ Qs,
        const float* __restrict__ Du, const float* __restrict__ Db,
        const float* __restrict__ Dt, const float* __restrict__ Dsm,
        const float* __restrict__ dwm, const float* __restrict__ dem,
        float* __restrict__ part) {
    constexpr float C4 = 0.0183156393f;   // exp(-4)
    int slot = blockIdx.x, b = blockIdx.y;
    int dm = slot >> 2, chunk = slot & 3;
    const float* D  = (dm == 0) ? Du : (dm == 1) ? Db : (dm == 2) ? Dt : Dsm;
    int Ld          = (dm == 0) ? 512 : (dm == 1) ? 511 : (dm == 2) ? 510 : 10;
    const float* md = (dm < 3) ? dwm : dem;
    int md_stride   = (dm < 3) ? 512 : 10;
    int chunkRows   = (dm < 3) ? 128 : 16;
    int t = threadIdx.x, qr = t >> 2, g = t & 3;

    float4 qreg[8];
    const float* qptr = nullptr;
    if (qr < 20)      qptr = Qu + (size_t)(b * 20 + qr) * CH;
    else if (qr < 39) qptr = Qb + (size_t)(b * 19 + (qr - 20)) * CH;
    else if (qr < 57) qptr = Qt + (size_t)(b * 18 + (qr - 39)) * CH;
    else if (qr < 62) qptr = Qs + (size_t)(b * 5 + (qr - 57)) * CH;
    if (qptr) {
        const float4* q4 = reinterpret_cast<const float4*>(qptr);
        #pragma unroll
        for (int i = 0; i < 8; i++) qreg[i] = q4[g + 4 * i];
    } else {
        #pragma unroll
        for (int i = 0; i < 8; i++) qreg[i] = make_float4(0.f, 0.f, 0.f, 0.f);
    }

    float acc[NB];
    #pragma unroll
    for (int k = 0; k < NB; k++) acc[k] = 0.f;

    __shared__ alignas(16) float Ds[16][CH];
    __shared__ float msk[16];

    int ld_begin = chunk * chunkRows;
    for (int ld0 = ld_begin; ld0 < ld_begin + chunkRows; ld0 += 16) {
        __syncthreads();
        #pragma unroll
        for (int i = t; i < 512; i += 256) {
            int r = i >> 5, c = i & 31;
            int row = ld0 + r;
            float4 v = make_float4(0.f, 0.f, 0.f, 0.f);
            if (row < Ld)
                v = reinterpret_cast<const float4*>(D + ((size_t)b * Ld + row) * CH)[c];
            reinterpret_cast<float4*>(&Ds[r][0])[c] = v;
        }
        if (t < 16) {
            int rr = ld0 + t;
            msk[t] = (rr < Ld) ? md[(size_t)b * md_stride + rr] : 0.f;
        }
        __syncthreads();
        #pragma unroll
        for (int rb = 0; rb < 4; rb++) {
            float mys = 0.f, mym = 0.f;
            #pragma unroll
            for (int k = 0; k < 4; k++) {
                int r = rb * 4 + k;
                const float4* dp = reinterpret_cast<const float4*>(&Ds[r][0]);
                float s = 0.f;
                #pragma unroll
                for (int i = 0; i < 8; i++) {
                    float4 d4 = dp[g + 4 * i];
                    float4 q4 = qreg[i];
                    s += d4.x * q4.x + d4.y * q4.y + d4.z * q4.z + d4.w * q4.w;
                }
                s += __shfl_xor_sync(0xffffffffu, s, 1);
                s += __shfl_xor_sync(0xffffffffu, s, 2);
                if (g == k) { mys = s; mym = msk[r]; }
            }
            // telescoping chain on own row: kernels idx 1..10 (mu 0.9..-0.9), center idx5
            float x4 = mys - 0.1f;
            float E  = __expf(-50.f * x4 * x4);
            float U  = __expf(20.f * x4 - 2.f);
            float R  = __expf(-20.f * x4 - 2.f);
            acc[5] += mym * E;
            float Eu = E, Uc = U;
            #pragma unroll
            for (int j = 4; j >= 1; j--) { Eu *= Uc; Uc *= C4; acc[j] += mym * Eu; }
            float Ev = E, Rc = R;
            #pragma unroll
            for (int j = 6; j <= 10; j++) { Ev *= Rc; Rc *= C4; acc[j] += mym * Ev; }
            // exact-match kernel (mu=1, sigma=1e-3), direct with skip
            float d0 = mys - 1.0f;
            float a0 = d0 * d0 * -500000.f;
            if (a0 > -60.f) acc[0] += mym * __expf(a0);
        }
    }
    // cross-lane (within group of 4) sums
    #pragma unroll
    for (int k = 0; k < NB; k++) {
        float v = acc[k];
        v += __shfl_xor_sync(0xffffffffu, v, 1);
        v += __shfl_xor_sync(0xffffffffu, v, 2);
        acc[k] = v;
    }
    size_t base = ((size_t)slot * BB + b) * (QR_TOT * NB) + (size_t)qr * NB;
    part[base + g]     = acc[g];
    part[base + g + 4] = acc[g + 4];
    if (g + 8 < NB) part[base + g + 8] = acc[g + 8];
}

// ---- final ----
__global__ void __launch_bounds__(256) final_kernel(
        const float* __restrict__ part, const float* __restrict__ qwm,
        const float* __restrict__ qem, const float* __restrict__ dW,
        const float* __restrict__ dB, float* __restrict__ out) {
    int b = blockIdx.x, t = threadIdx.x;
    float local = 0.f;
    for (int p = 0; p < NPAIR; p++) {
        int qsrc = c_pq[p], dmat = c_pd[p];
        int Lqp = c_qlen[qsrc], off = c_qoff[qsrc];
        int slot = c_dslot[dmat], nch = c_dnch[dmat];
        int tot = Lqp * NB;
        for (int idx = t; idx < tot; idx += 256) {
            int lq = idx / NB, k = idx - lq * NB;
            int row = off + lq;
            float s = 0.f;
            for (int c = 0; c < nch; c++)
                s += part[((size_t)(slot + c) * BB + b) * (QR_TOT * NB) + row * NB + k];
            float mq = (qsrc < 3) ? qwm[b * 20 + lq] : qem[b * 5 + lq];
            local += dW[p * NB + k] * (__logf(fmaxf(s, 1e-10f)) * 0.01f * mq);
        }
    }
    #pragma unroll
    for (int off = 16; off > 0; off >>= 1) local += __shfl_xor_sync(0xffffffffu, local, off);
    __shared__ float r8[8];
    if ((t & 31) == 0) r8[t >> 5] = local;
    __syncthreads();
    if (t == 0) {
        float s = 0.f;
        #pragma unroll
        for (int w = 0; w < 8; w++) s += r8[w];
        out[b] = tanhf(s + dB[0]);
    }
}

// ---- launcher (round-12 schedule) ----
extern "C" void kernel_launch(void* const* d_in, const int* in_sizes, int n_in,
                              void* d_out, int out_size) {
    const int*   qwt = (const int*)d_in[0];
    const float* qwm = (const float*)d_in[1];
    const int*   qei = (const int*)d_in[2];
    const int*   qet = (const int*)d_in[3];
    const int*   qew = (const int*)d_in[4];
    const float* qem = (const float*)d_in[5];
    const int*   dwt = (const int*)d_in[6];
    const float* dwm = (const float*)d_in[7];
    const int*   dei = (const int*)d_in[8];
    const int*   det = (const int*)d_in[9];
    const int*   dew = (const int*)d_in[10];
    const float* dem = (const float*)d_in[11];
    const float* wrd = (const float*)d_in[12];
    const float* ent = (const float*)d_in[13];
    const float* car = (const float*)d_in[14];
    const float* bowW = (const float*)d_in[15];
    const float* bowB = (const float*)d_in[16];
    const float* cuW = (const float*)d_in[17];
    const float* cuB = (const float*)d_in[18];
    const float* cbW = (const float*)d_in[19];
    const float* cbB = (const float*)d_in[20];
    const float* ctW = (const float*)d_in[21];
    const float* ctB = (const float*)d_in[22];
    const float* cdW = (const float*)d_in[23];
    const float* cdB = (const float*)d_in[24];
    const float* dfW = (const float*)d_in[25];
    const float* dfB = (const float*)d_in[26];
    float* out = (float*)d_out;

    float* S = nullptr;
    cudaGetSymbolAddress((void**)&S, g_scratch);
    float* qw    = S + OFF_QW;
    float* dw    = S + OFF_DW;
    float* qbow  = S + OFF_QBOW;
    float* dbow  = S + OFF_DBOW;
    float* qu    = S + OFF_QU;
    float* qb    = S + OFF_QB;
    float* qt    = S + OFF_QT;
    float* du    = S + OFF_DU;
    float* db    = S + OFF_DB;
    float* dt    = S + OFF_DT;
    float* qs    = S + OFF_QS;
    float* ds    = S + OFF_DS;
    float* cs1   = S + OFF_CS1;
    float* cs8   = S + OFF_CS8;
    float* econ  = S + OFF_ECONV;
    float* partP = S + OFF_PART;

    static cudaStream_t sA = nullptr, sB = nullptr;
    static cudaEvent_t evF = nullptr, evB = nullptr, evA = nullptr;
    if (sA == nullptr) {
        cudaStreamCreateWithFlags(&sA, cudaStreamNonBlocking);
        cudaStreamCreateWithFlags(&sB, cudaStreamNonBlocking);
        cudaEventCreateWithFlags(&evF, cudaEventDisableTiming);
        cudaEventCreateWithFlags(&evB, cudaEventDisableTiming);
        cudaEventCreateWithFlags(&evA, cudaEventDisableTiming);
        cudaFuncSetAttribute(wordconv_bf16_kernel,
                             cudaFuncAttributeMaxDynamicSharedMemorySize, WORD_SMEM);
        cudaFuncSetAttribute(entconv_bf16_kernel,
                             cudaFuncAttributeMaxDynamicSharedMemorySize, ENT_SMEM);
    }

    // FORK from capture-origin stream
    cudaEventRecord(evF, 0);
    cudaStreamWaitEvent(sA, evF, 0);
    cudaStreamWaitEvent(sB, evF, 0);

    // main: word convs start immediately (token-direct)
    wordconv_bf16_kernel<<<dim3(15, BB), 256, WORD_SMEM>>>(dwt, qwt, wrd,
                                                           cuW, cuB, cbW, cbB, ctW, ctB,
                                                           du, qu, db, qb, dt, qt);
    // stream A: entity desc conv (token-direct)
    entconv_bf16_kernel<<<dim3(2, BB), 256, ENT_SMEM, sA>>>(qet, det, wrd, cdW, cdB, econ);
    // stream B: gathers -> colsum -> bows
    gather_kernel<<<(BB * LQ * 75 + 255) / 256, 256, 0, sB>>>(wrd, qwt, qw, BB * LQ);
    gather_kernel<<<(BB * LD * 75 + 255) / 256, 256, 0, sB>>>(wrd, dwt, dw, BB * LD);
    colsum_kernel<<<dim3(NCD + 1, BB), 128, 0, sB>>>(dw, qw, cs8, cs1);
    bow2_kernel<<<BB, 128, 0, sB>>>(cs1, 1, LQ, bowW, bowB, qbow);
    bow2_kernel<<<BB, 128, 0, sB>>>(cs8, NCD, LD, bowW, bowB, dbow);
    // entity_post on A after B's bows are ready
    cudaEventRecord(evB, sB);
    cudaStreamWaitEvent(sA, evB, 0);
    entity_post_kernel<<<dim3(EQ + ED, BB), 128, 0, sA>>>(qei, qew, qbow, dei, dew, dbow,
                                                          ent, car, econ, qs, ds);
    // JOIN A into main (main already ordered after wordconv)
    cudaEventRecord(evA, sA);
    cudaStreamWaitEvent(0, evA, 0);

    pool_all_kernel<<<dim3(PSLOTS, BB), 256>>>(qu, qb, qt, qs, du, db, dt, ds,
                                               dwm, dem, partP);
    final_kernel<<<BB, 256>>>(partP, qwm, qem, dfW, dfB, out);
}